// round 10
// baseline (speedup 1.0000x reference)
#include <cuda_runtime.h>
#include <cuda_bf16.h>
#include <cstdint>

#define N_NODES 100000
#define N_EDGES 800000
#define C 128
#define EPS_BN 1e-5f
#define NB ((N_NODES + 255) / 256)

// ---------------- device scratch (no allocs allowed) ----------------
__device__ unsigned short g_aggh[N_NODES * C];   // mean, bf16 hi plane
__device__ unsigned short g_aggl[N_NODES * C];   // mean, bf16 lo plane
__device__ float g_h1[N_NODES * C];
__device__ float g_h2[N_NODES * C];
__device__ unsigned short g_Bw[3][2][128 * 256]; // [layer][hi/lo][n][k] bf16
__device__ unsigned short g_Bh[2][128 * 128];    // head [hi/lo][n][k]
__device__ float g_bh1p[C];
__device__ float g_sum[C];
__device__ float g_sumsq[C];
__device__ float g_scale[C];
__device__ float g_shift[C];
__device__ int g_src[N_EDGES];
__device__ int g_dst[N_EDGES];
__device__ int g_esrc[N_EDGES];
__device__ int g_cnt[N_NODES];
__device__ int g_rowptr[N_NODES + 1];
__device__ int g_cursor[N_NODES];
__device__ int g_bsum[NB];
__device__ int g_is64;

// ---------------- helpers ----------------
__device__ __forceinline__ uint32_t smem_u32(const void* p) {
    uint32_t a;
    asm("{ .reg .u64 t; cvta.to.shared.u64 t, %1; cvt.u32.u64 %0, t; }" : "=r"(a) : "l"(p));
    return a;
}
__device__ __forceinline__ void ldm4(uint32_t* r, uint32_t addr) {
    asm volatile("ldmatrix.sync.aligned.m8n8.x4.shared.b16 {%0,%1,%2,%3}, [%4];"
                 : "=r"(r[0]), "=r"(r[1]), "=r"(r[2]), "=r"(r[3]) : "r"(addr));
}
__device__ __forceinline__ void mma16816(float* c, const uint32_t* a, uint32_t b0, uint32_t b1) {
    asm volatile(
        "mma.sync.aligned.m16n8k16.row.col.f32.bf16.bf16.f32 "
        "{%0,%1,%2,%3}, {%4,%5,%6,%7}, {%8,%9}, {%0,%1,%2,%3};"
        : "+f"(c[0]), "+f"(c[1]), "+f"(c[2]), "+f"(c[3])
        : "r"(a[0]), "r"(a[1]), "r"(a[2]), "r"(a[3]), "r"(b0), "r"(b1));
}
__device__ __forceinline__ unsigned short bfbits(__nv_bfloat16 h) {
    return *reinterpret_cast<unsigned short*>(&h);
}
__device__ __forceinline__ void cp16(uint32_t dst, const void* src) {
    asm volatile("cp.async.cg.shared.global [%0], [%1], 16;" :: "r"(dst), "l"(src));
}

// ---------------- edge dtype detection ----------------
__global__ void detect_kernel(const int* __restrict__ w) {
    __shared__ int acc[256];
    int tid = threadIdx.x;
    int v = 0;
    for (int i = tid; i < 1024; i += 256) v |= w[2 * i + 1];
    acc[tid] = v;
    __syncthreads();
    for (int s = 128; s > 0; s >>= 1) {
        if (tid < s) acc[tid] |= acc[tid + s];
        __syncthreads();
    }
    if (tid == 0) g_is64 = (acc[0] == 0) ? 1 : 0;
}

// ---------------- CSR build ----------------
__global__ void zero_cnt_kernel() {
    int i = blockIdx.x * blockDim.x + threadIdx.x;
    if (i < N_NODES) g_cnt[i] = 0;
}

__global__ void decode_hist_kernel(const int* __restrict__ w) {
    int e = blockIdx.x * blockDim.x + threadIdx.x;
    if (e >= N_EDGES) return;
    int s, d;
    if (g_is64) {
        s = w[2 * e];
        d = w[2 * (N_EDGES + e)];
    } else {
        s = w[e];
        d = w[N_EDGES + e];
    }
    g_src[e] = s;
    g_dst[e] = d;
    atomicAdd(&g_cnt[d], 1);
}

__global__ void bsum_kernel() {
    __shared__ int sm[256];
    int i = blockIdx.x * 256 + threadIdx.x;
    sm[threadIdx.x] = (i < N_NODES) ? g_cnt[i] : 0;
    __syncthreads();
    for (int s = 128; s > 0; s >>= 1) {
        if (threadIdx.x < s) sm[threadIdx.x] += sm[threadIdx.x + s];
        __syncthreads();
    }
    if (threadIdx.x == 0) g_bsum[blockIdx.x] = sm[0];
}

__global__ void scan_bsum_kernel() {
    __shared__ int sm[512];
    int t = threadIdx.x;
    int val = (t < NB) ? g_bsum[t] : 0;
    sm[t] = val;
    __syncthreads();
    for (int off = 1; off < 512; off <<= 1) {
        int x = (t >= off) ? sm[t - off] : 0;
        __syncthreads();
        sm[t] += x;
        __syncthreads();
    }
    if (t < NB) g_bsum[t] = sm[t] - val;
}

__global__ void rowptr_kernel() {
    __shared__ int sm[256];
    int t = threadIdx.x;
    int i = blockIdx.x * 256 + t;
    int c = (i < N_NODES) ? g_cnt[i] : 0;
    sm[t] = c;
    __syncthreads();
    for (int off = 1; off < 256; off <<= 1) {
        int x = (t >= off) ? sm[t - off] : 0;
        __syncthreads();
        sm[t] += x;
        __syncthreads();
    }
    if (i < N_NODES) {
        int rp = g_bsum[blockIdx.x] + sm[t] - c;
        g_rowptr[i] = rp;
        g_cursor[i] = rp;
        if (i == N_NODES - 1) g_rowptr[N_NODES] = rp + c;
    }
}

__global__ void fill_kernel() {
    int e = blockIdx.x * blockDim.x + threadIdx.x;
    if (e >= N_EDGES) return;
    int pos = atomicAdd(&g_cursor[g_dst[e]], 1);
    g_esrc[pos] = g_src[e];
}

// ---------------- pack weights ----------------
__global__ void pack_all_kernel(const float* __restrict__ Wn0, const float* __restrict__ Wr0,
                                const float* __restrict__ Wn1, const float* __restrict__ Wr1,
                                const float* __restrict__ Wn2, const float* __restrict__ Wr2) {
    int idx = blockIdx.x * blockDim.x + threadIdx.x;
    if (idx >= 3 * 128 * 256) return;
    int layer = idx / (128 * 256);
    int r = idx % (128 * 256);
    int n = r / 256, k = r % 256;
    const float* Wn = (layer == 0) ? Wn0 : (layer == 1) ? Wn1 : Wn2;
    const float* Wr = (layer == 0) ? Wr0 : (layer == 1) ? Wr1 : Wr2;
    float w = (k < C) ? Wn[n * C + k] : Wr[n * C + (k - C)];
    __nv_bfloat16 hi = __float2bfloat16(w);
    __nv_bfloat16 lo = __float2bfloat16(w - __bfloat162float(hi));
    g_Bw[layer][0][r] = bfbits(hi);
    g_Bw[layer][1][r] = bfbits(lo);
}

__global__ void pack_head_kernel(const float* __restrict__ Wh1,
                                 const float* __restrict__ bh1) {
    int idx = blockIdx.x * blockDim.x + threadIdx.x;
    if (idx < 128 * 128) {
        int n = idx / 128, k = idx % 128;
        float w = (n < 64) ? Wh1[n * C + k] : 0.0f;
        __nv_bfloat16 hi = __float2bfloat16(w);
        __nv_bfloat16 lo = __float2bfloat16(w - __bfloat162float(hi));
        g_Bh[0][idx] = bfbits(hi);
        g_Bh[1][idx] = bfbits(lo);
    }
    if (idx < C) g_bh1p[idx] = (idx < 64) ? bh1[idx] : 0.0f;
}

// ---------------- CSR aggregation -> bf16 hi/lo planes ----------------
template <bool XFORM>
__global__ void agg_kernel(const float* __restrict__ h) {
    int gt = blockIdx.x * blockDim.x + threadIdx.x;
    int w = gt >> 5;
    int lane = gt & 31;
    if (w >= N_NODES) return;
    int beg = g_rowptr[w], end = g_rowptr[w + 1];
    float4 acc = make_float4(0.f, 0.f, 0.f, 0.f);
    float4 sc, sh;
    if (XFORM) {
        sc = reinterpret_cast<const float4*>(g_scale)[lane];
        sh = reinterpret_cast<const float4*>(g_shift)[lane];
    }
    int e = beg;
    for (; e + 1 < end; e += 2) {
        int s0 = __ldg(&g_esrc[e]);
        int s1 = __ldg(&g_esrc[e + 1]);
        float4 v0 = *reinterpret_cast<const float4*>(h + (size_t)s0 * C + lane * 4);
        float4 v1 = *reinterpret_cast<const float4*>(h + (size_t)s1 * C + lane * 4);
        if (XFORM) {
            v0.x = fmaxf(fmaf(v0.x, sc.x, sh.x), 0.f);
            v0.y = fmaxf(fmaf(v0.y, sc.y, sh.y), 0.f);
            v0.z = fmaxf(fmaf(v0.z, sc.z, sh.z), 0.f);
            v0.w = fmaxf(fmaf(v0.w, sc.w, sh.w), 0.f);
            v1.x = fmaxf(fmaf(v1.x, sc.x, sh.x), 0.f);
            v1.y = fmaxf(fmaf(v1.y, sc.y, sh.y), 0.f);
            v1.z = fmaxf(fmaf(v1.z, sc.z, sh.z), 0.f);
            v1.w = fmaxf(fmaf(v1.w, sc.w, sh.w), 0.f);
        }
        acc.x += v0.x + v1.x;
        acc.y += v0.y + v1.y;
        acc.z += v0.z + v1.z;
        acc.w += v0.w + v1.w;
    }
    if (e < end) {
        int s0 = __ldg(&g_esrc[e]);
        float4 v0 = *reinterpret_cast<const float4*>(h + (size_t)s0 * C + lane * 4);
        if (XFORM) {
            v0.x = fmaxf(fmaf(v0.x, sc.x, sh.x), 0.f);
            v0.y = fmaxf(fmaf(v0.y, sc.y, sh.y), 0.f);
            v0.z = fmaxf(fmaf(v0.z, sc.z, sh.z), 0.f);
            v0.w = fmaxf(fmaf(v0.w, sc.w, sh.w), 0.f);
        }
        acc.x += v0.x;
        acc.y += v0.y;
        acc.z += v0.z;
        acc.w += v0.w;
    }
    float rd = 1.f / fmaxf((float)(end - beg), 1.f);
    float v[4] = {acc.x * rd, acc.y * rd, acc.z * rd, acc.w * rd};
    uint32_t hw[2], lw[2];
#pragma unroll
    for (int j = 0; j < 2; j++) {
        __nv_bfloat16 h0 = __float2bfloat16(v[2 * j]);
        __nv_bfloat16 h1 = __float2bfloat16(v[2 * j + 1]);
        __nv_bfloat16 l0 = __float2bfloat16(v[2 * j] - __bfloat162float(h0));
        __nv_bfloat16 l1 = __float2bfloat16(v[2 * j + 1] - __bfloat162float(h1));
        hw[j] = (uint32_t)bfbits(h0) | ((uint32_t)bfbits(h1) << 16);
        lw[j] = (uint32_t)bfbits(l0) | ((uint32_t)bfbits(l1) << 16);
    }
    *reinterpret_cast<uint2*>(g_aggh + (size_t)w * C + lane * 4) = make_uint2(hw[0], hw[1]);
    *reinterpret_cast<uint2*>(g_aggl + (size_t)w * C + lane * 4) = make_uint2(lw[0], lw[1]);
}

// ---------------- pipelined mma.sync fused GEMM ----------------
// smem: A_hi 18432 | A_lo 18432 | B0 (hi+lo) 36864 | B1 36864 | bias 512 | scale 512 | shift 512
#define AS_HI 0
#define AS_LO 18432
#define BS0 36864
#define BS1 73728
#define SMBIAS 110592
#define SMSC 111104
#define SMSH 111616
#define SM_TOTAL 112128
#define STAGE_LD 132

template <int KS, bool SAGE, bool XFORM, bool RELU_OUT, bool STATS>
__global__ void __launch_bounds__(256, 2)
gemm_mma_kernel(const float* __restrict__ A, const unsigned short* __restrict__ Bpk,
                const float* __restrict__ bias, float* __restrict__ out) {
    constexpr int NCHUNK = KS / 64;
    extern __shared__ char sm[];
    uint32_t smb = smem_u32(sm);
    int tid = threadIdx.x;
    int wid = tid >> 5;
    int lane = tid & 31;
    int row0 = blockIdx.x * 128;

    if (tid < 32) {
        reinterpret_cast<float4*>(sm + SMBIAS)[tid] = reinterpret_cast<const float4*>(bias)[tid];
        if (XFORM) {
            reinterpret_cast<float4*>(sm + SMSC)[tid] = reinterpret_cast<const float4*>(g_scale)[tid];
            reinterpret_cast<float4*>(sm + SMSH)[tid] = reinterpret_cast<const float4*>(g_shift)[tid];
        }
    }
    __syncthreads();   // FIX (R8 bug): scale/shift/bias written by warp 0, read by ALL in storeA(0)

    int arow = tid >> 1;
    int ahalf = tid & 1;
    int grow = row0 + arow;
    bool valid = grow < N_NODES;

    int m0 = (wid >> 1) * 32;
    int n0 = (wid & 1) * 64;

    uint32_t a_base[2], b_base[4];
#pragma unroll
    for (int mi = 0; mi < 2; mi++)
        a_base[mi] = smb + AS_HI + (uint32_t)(m0 + mi * 16 + (lane & 15)) * 144u +
                     ((lane >> 4) * 8u) * 2u;
#pragma unroll
    for (int g = 0; g < 4; g++) {
        uint32_t nidx = (uint32_t)(n0 + g * 16 + ((lane >> 4) << 3) + (lane & 7));
        uint32_t koff = (((lane >> 3) & 1) * 8u) * 2u;
        b_base[g] = smb + BS0 + nidx * 144u + koff;
    }

    float acc[2][8][4];
#pragma unroll
    for (int mi = 0; mi < 2; mi++)
#pragma unroll
        for (int ni = 0; ni < 8; ni++)
#pragma unroll
            for (int r = 0; r < 4; r++) acc[mi][ni][r] = 0.f;

    uint4 ar[8];
    auto loadA = [&](int chunk) {
        if (SAGE && chunk < 2) {
            if (valid) {
                size_t off = (size_t)grow * C + chunk * 64 + ahalf * 32;
                const uint4* ph = reinterpret_cast<const uint4*>(g_aggh + off);
                const uint4* pl = reinterpret_cast<const uint4*>(g_aggl + off);
#pragma unroll
                for (int j = 0; j < 4; j++) { ar[j] = ph[j]; ar[4 + j] = pl[j]; }
            } else {
#pragma unroll
                for (int j = 0; j < 8; j++) ar[j] = make_uint4(0, 0, 0, 0);
            }
        } else {
            int col0 = (SAGE ? chunk * 64 - 128 : chunk * 64) + ahalf * 32;
            if (valid) {
                const uint4* p = reinterpret_cast<const uint4*>(A + (size_t)grow * C + col0);
#pragma unroll
                for (int j = 0; j < 8; j++) ar[j] = p[j];
            } else {
#pragma unroll
                for (int j = 0; j < 8; j++) ar[j] = make_uint4(0, 0, 0, 0);
            }
        }
    };
    auto storeA = [&](int chunk) {
        if (SAGE && chunk < 2) {
            uint32_t off = arow * 144u + ahalf * 64u;
#pragma unroll
            for (int j = 0; j < 4; j++) {
                *reinterpret_cast<uint4*>(sm + AS_HI + off + j * 16) = ar[j];
                *reinterpret_cast<uint4*>(sm + AS_LO + off + j * 16) = ar[4 + j];
            }
        } else {
            int col0 = (SAGE ? chunk * 64 - 128 : chunk * 64) + ahalf * 32;
            const float* ssc = reinterpret_cast<const float*>(sm + SMSC);
            const float* ssh = reinterpret_cast<const float*>(sm + SMSH);
#pragma unroll
            for (int j8 = 0; j8 < 4; j8++) {
                float v[8];
                *reinterpret_cast<uint4*>(&v[0]) = ar[2 * j8];
                *reinterpret_cast<uint4*>(&v[4]) = ar[2 * j8 + 1];
                if (XFORM && valid) {
                    int cb = col0 + j8 * 8;
#pragma unroll
                    for (int j = 0; j < 8; j++)
                        v[j] = fmaxf(fmaf(v[j], ssc[cb + j], ssh[cb + j]), 0.f);
                }
                uint32_t hw[4], lw[4];
#pragma unroll
                for (int j = 0; j < 4; j++) {
                    __nv_bfloat16 h0 = __float2bfloat16(v[2 * j]);
                    __nv_bfloat16 h1 = __float2bfloat16(v[2 * j + 1]);
                    __nv_bfloat16 l0 = __float2bfloat16(v[2 * j] - __bfloat162float(h0));
                    __nv_bfloat16 l1 = __float2bfloat16(v[2 * j + 1] - __bfloat162float(h1));
                    hw[j] = (uint32_t)bfbits(h0) | ((uint32_t)bfbits(h1) << 16);
                    lw[j] = (uint32_t)bfbits(l0) | ((uint32_t)bfbits(l1) << 16);
                }
                uint32_t off = arow * 144u + (ahalf * 32 + j8 * 8) * 2u;
                *reinterpret_cast<uint4*>(sm + AS_HI + off) = make_uint4(hw[0], hw[1], hw[2], hw[3]);
                *reinterpret_cast<uint4*>(sm + AS_LO + off) = make_uint4(lw[0], lw[1], lw[2], lw[3]);
            }
        }
    };
    auto loadB = [&](int chunk) {
        int bufo = (chunk & 1) ? BS1 : BS0;
#pragma unroll
        for (int it = 0; it < 8; it++) {
            int i = tid + it * 256;           // 0..2047 ; <1024 hi, else lo
            int plane = i >> 10;
            int ii = i & 1023;
            int r = ii >> 3, cc = ii & 7;
            const unsigned short* src = Bpk + (size_t)plane * 128 * KS + (size_t)r * KS +
                                        chunk * 64 + cc * 8;
            uint32_t dst = smb + bufo + plane * 18432 + r * 144 + cc * 16;
            cp16(dst, src);
        }
        asm volatile("cp.async.commit_group;" ::: "memory");
    };

    loadA(0);
    loadB(0);

#pragma unroll
    for (int chunk = 0; chunk < NCHUNK; chunk++) {
        storeA(chunk);
        if (chunk + 1 < NCHUNK) {
            loadA(chunk + 1);
            loadB(chunk + 1);
            asm volatile("cp.async.wait_group 1;" ::: "memory");
        } else {
            asm volatile("cp.async.wait_group 0;" ::: "memory");
        }
        __syncthreads();

        uint32_t bufo = (chunk & 1) ? (BS1 - BS0) : 0u;
#pragma unroll
        for (int ks = 0; ks < 4; ks++) {
            int kl = ks * 16;
            uint32_t ah[2][4], al[2][4], bh[4][4], bl[4][4];
#pragma unroll
            for (int mi = 0; mi < 2; mi++) {
                ldm4(ah[mi], a_base[mi] + kl * 2);
                ldm4(al[mi], a_base[mi] + 18432 + kl * 2);
            }
#pragma unroll
            for (int g = 0; g < 4; g++) {
                ldm4(bh[g], b_base[g] + bufo + kl * 2);
                ldm4(bl[g], b_base[g] + bufo + 18432 + kl * 2);
            }
#pragma unroll
            for (int mi = 0; mi < 2; mi++)
#pragma unroll
                for (int g = 0; g < 4; g++) {
                    mma16816(acc[mi][2 * g + 0], ah[mi], bh[g][0], bh[g][1]);
                    mma16816(acc[mi][2 * g + 1], ah[mi], bh[g][2], bh[g][3]);
                    mma16816(acc[mi][2 * g + 0], ah[mi], bl[g][0], bl[g][1]);
                    mma16816(acc[mi][2 * g + 1], ah[mi], bl[g][2], bl[g][3]);
                    mma16816(acc[mi][2 * g + 0], al[mi], bh[g][0], bh[g][1]);
                    mma16816(acc[mi][2 * g + 1], al[mi], bh[g][2], bh[g][3]);
                }
        }
        __syncthreads();
    }

    // epilogue: bias (+relu), stage to smem (overlaying A/B regions)
    float* stage = reinterpret_cast<float*>(sm);
    const float* sbias = reinterpret_cast<const float*>(sm + SMBIAS);
    int qr = lane >> 2, qc = lane & 3;
#pragma unroll
    for (int mi = 0; mi < 2; mi++) {
        int mA = m0 + mi * 16 + qr;
        int mB = mA + 8;
        bool vA = (row0 + mA) < N_NODES;
        bool vB = (row0 + mB) < N_NODES;
#pragma unroll
        for (int ni = 0; ni < 8; ni++) {
            int n = n0 + ni * 8 + qc * 2;
            float2 pA, pB;
            pA.x = acc[mi][ni][0] + sbias[n];
            pA.y = acc[mi][ni][1] + sbias[n + 1];
            pB.x = acc[mi][ni][2] + sbias[n];
            pB.y = acc[mi][ni][3] + sbias[n + 1];
            if (RELU_OUT) {
                pA.x = fmaxf(pA.x, 0.f); pA.y = fmaxf(pA.y, 0.f);
                pB.x = fmaxf(pB.x, 0.f); pB.y = fmaxf(pB.y, 0.f);
            }
            if (!vA) pA = make_float2(0.f, 0.f);
            if (!vB) pB = make_float2(0.f, 0.f);
            *reinterpret_cast<float2*>(stage + mA * STAGE_LD + n) = pA;
            *reinterpret_cast<float2*>(stage + mB * STAGE_LD + n) = pB;
        }
    }
    __syncthreads();

    if (STATS && tid < C) {
        float s = 0.f, q = 0.f;
        for (int r = 0; r < 128; r++) {
            float v = stage[r * STAGE_LD + tid];
            s += v;
            q += v * v;
        }
        atomicAdd(&g_sum[tid], s);
        atomicAdd(&g_sumsq[tid], q);
    }

    for (int idx = tid; idx < 128 * 32; idx += 256) {
        int r = idx >> 5, c4 = idx & 31;
        int row = row0 + r;
        if (row >= N_NODES) continue;
        *reinterpret_cast<float4*>(out + (size_t)row * C + c4 * 4) =
            *reinterpret_cast<const float4*>(stage + r * STAGE_LD + c4 * 4);
    }
}

__global__ void bnparam_kernel(const float* __restrict__ g, const float* __restrict__ be) {
    int c = threadIdx.x;
    if (c >= C) return;
    float m = g_sum[c] / (float)N_NODES;
    float v = g_sumsq[c] / (float)N_NODES - m * m;
    float sc = g[c] * rsqrtf(fmaxf(v, 0.f) + EPS_BN);
    g_scale[c] = sc;
    g_shift[c] = be[c] - m * sc;
    g_sum[c] = 0.f;
    g_sumsq[c] = 0.f;
}

// ---------------- head-2 ----------------
__global__ void head2_kernel(const float* __restrict__ h, const float* __restrict__ Wh2,
                             const float* __restrict__ bh2, float* __restrict__ out) {
    int gtid = blockIdx.x * blockDim.x + threadIdx.x;
    int w = gtid >> 5;
    int lane = gtid & 31;
    if (w >= N_NODES) return;
    float2 v = *reinterpret_cast<const float2*>(h + (size_t)w * C + lane * 2);
    float s0 = v.x * Wh2[lane * 2] + v.y * Wh2[lane * 2 + 1];
    float s1 = v.x * Wh2[64 + lane * 2] + v.y * Wh2[64 + lane * 2 + 1];
#pragma unroll
    for (int o = 16; o > 0; o >>= 1) {
        s0 += __shfl_down_sync(0xffffffffu, s0, o);
        s1 += __shfl_down_sync(0xffffffffu, s1, o);
    }
    if (lane == 0) {
        out[(size_t)w * 2 + 0] = s0 + bh2[0];
        out[(size_t)w * 2 + 1] = s1 + bh2[1];
    }
}

// ---------------- launch ----------------
extern "C" void kernel_launch(void* const* d_in, const int* in_sizes, int n_in,
                              void* d_out, int out_size) {
    const float* x = (const float*)d_in[0];
    const int* ei32 = (const int*)d_in[1];
    const float* Wn[3] = {(const float*)d_in[2], (const float*)d_in[7], (const float*)d_in[12]};
    const float* bn[3] = {(const float*)d_in[3], (const float*)d_in[8], (const float*)d_in[13]};
    const float* Wr[3] = {(const float*)d_in[4], (const float*)d_in[9], (const float*)d_in[14]};
    const float* ga[3] = {(const float*)d_in[5], (const float*)d_in[10], (const float*)d_in[15]};
    const float* be[3] = {(const float*)d_in[6], (const float*)d_in[11], (const float*)d_in[16]};
    const float* Wh1 = (const float*)d_in[17];
    const float* bh1 = (const float*)d_in[18];
    const float* Wh2 = (const float*)d_in[19];
    const float* bh2 = (const float*)d_in[20];
    float* out = (float*)d_out;

    float *p_h1, *p_h2, *p_bh1p;
    unsigned short *p_Bw, *p_Bh;
    cudaGetSymbolAddress((void**)&p_h1, g_h1);
    cudaGetSymbolAddress((void**)&p_h2, g_h2);
    cudaGetSymbolAddress((void**)&p_Bw, g_Bw);
    cudaGetSymbolAddress((void**)&p_Bh, g_Bh);
    cudaGetSymbolAddress((void**)&p_bh1p, g_bh1p);

    cudaFuncSetAttribute(gemm_mma_kernel<256, true, false, false, true>,
                         cudaFuncAttributeMaxDynamicSharedMemorySize, SM_TOTAL);
    cudaFuncSetAttribute(gemm_mma_kernel<256, true, true, false, true>,
                         cudaFuncAttributeMaxDynamicSharedMemorySize, SM_TOTAL);
    cudaFuncSetAttribute(gemm_mma_kernel<128, false, true, true, false>,
                         cudaFuncAttributeMaxDynamicSharedMemorySize, SM_TOTAL);

    detect_kernel<<<1, 256>>>(ei32);
    zero_cnt_kernel<<<NB, 256>>>();
    decode_hist_kernel<<<(N_EDGES + 255) / 256, 256>>>(ei32);
    bsum_kernel<<<NB, 256>>>();
    scan_bsum_kernel<<<1, 512>>>();
    rowptr_kernel<<<NB, 256>>>();
    fill_kernel<<<(N_EDGES + 255) / 256, 256>>>();
    pack_all_kernel<<<(3 * 128 * 256 + 255) / 256, 256>>>(
        Wn[0], Wr[0], Wn[1], Wr[1], Wn[2], Wr[2]);
    pack_head_kernel<<<(128 * 128 + 255) / 256, 256>>>(Wh1, bh1);

    const int gemm_blocks = (N_NODES + 127) / 128;
    const int agg_blocks = (N_NODES * 32 + 255) / 256;
    float* bufs[2] = {p_h1, p_h2};
    const float* h_in = x;

    for (int l = 0; l < 3; l++) {
        float* h_out = bufs[l & 1];
        if (l == 0) {
            agg_kernel<false><<<agg_blocks, 256>>>(h_in);
            gemm_mma_kernel<256, true, false, false, true><<<gemm_blocks, 256, SM_TOTAL>>>(
                h_in, p_Bw, bn[l], h_out);
        } else {
            agg_kernel<true><<<agg_blocks, 256>>>(h_in);
            gemm_mma_kernel<256, true, true, false, true><<<gemm_blocks, 256, SM_TOTAL>>>(
                h_in, p_Bw + (size_t)l * 2 * 128 * 256, bn[l], h_out);
        }
        bnparam_kernel<<<1, 128>>>(ga[l], be[l]);
        h_in = h_out;
    }

    gemm_mma_kernel<128, false, true, true, false><<<gemm_blocks, 256, SM_TOTAL>>>(
        p_h1, p_Bh, p_bh1p, p_h2);
    head2_kernel<<<(N_NODES * 32 + 255) / 256, 256>>>(p_h2, Wh2, bh2, out);
}

// round 11
// speedup vs baseline: 1.1752x; 1.1752x over previous
#include <cuda_runtime.h>
#include <cuda_bf16.h>
#include <cstdint>

#define N_NODES 100000
#define N_EDGES 800000
#define C 128
#define EPS_BN 1e-5f
#define NB ((N_NODES + 255) / 256)

// ---------------- device scratch (no allocs allowed) ----------------
__device__ unsigned short g_aggh[N_NODES * C];   // mean, bf16 hi plane
__device__ unsigned short g_aggl[N_NODES * C];   // mean, bf16 lo plane
__device__ float g_h1[N_NODES * C];
__device__ float g_h2[N_NODES * C];
__device__ unsigned short g_Bw[3][2][128 * 256]; // [layer][hi/lo][n][k] bf16
__device__ unsigned short g_Bh[2][128 * 128];    // head [hi/lo][n][k]
__device__ float g_bh1p[C];
__device__ float g_sum[C];
__device__ float g_sumsq[C];
__device__ float g_scale[C];
__device__ float g_shift[C];
__device__ int g_src[N_EDGES];
__device__ int g_dst[N_EDGES];
__device__ int g_esrc[N_EDGES];
__device__ int g_cnt[N_NODES];
__device__ int g_rowptr[N_NODES + 1];
__device__ int g_cursor[N_NODES];
__device__ int g_bsum[NB];
__device__ int g_is64;

// ---------------- helpers ----------------
__device__ __forceinline__ uint32_t smem_u32(const void* p) {
    uint32_t a;
    asm("{ .reg .u64 t; cvta.to.shared.u64 t, %1; cvt.u32.u64 %0, t; }" : "=r"(a) : "l"(p));
    return a;
}
__device__ __forceinline__ void ldm4(uint32_t* r, uint32_t addr) {
    asm volatile("ldmatrix.sync.aligned.m8n8.x4.shared.b16 {%0,%1,%2,%3}, [%4];"
                 : "=r"(r[0]), "=r"(r[1]), "=r"(r[2]), "=r"(r[3]) : "r"(addr));
}
__device__ __forceinline__ void mma16816(float* c, const uint32_t* a, uint32_t b0, uint32_t b1) {
    asm volatile(
        "mma.sync.aligned.m16n8k16.row.col.f32.bf16.bf16.f32 "
        "{%0,%1,%2,%3}, {%4,%5,%6,%7}, {%8,%9}, {%0,%1,%2,%3};"
        : "+f"(c[0]), "+f"(c[1]), "+f"(c[2]), "+f"(c[3])
        : "r"(a[0]), "r"(a[1]), "r"(a[2]), "r"(a[3]), "r"(b0), "r"(b1));
}
__device__ __forceinline__ unsigned short bfbits(__nv_bfloat16 h) {
    return *reinterpret_cast<unsigned short*>(&h);
}

// ---------------- edge dtype detection ----------------
__global__ void detect_kernel(const int* __restrict__ w) {
    __shared__ int acc[256];
    int tid = threadIdx.x;
    int v = 0;
    for (int i = tid; i < 1024; i += 256) v |= w[2 * i + 1];
    acc[tid] = v;
    __syncthreads();
    for (int s = 128; s > 0; s >>= 1) {
        if (tid < s) acc[tid] |= acc[tid + s];
        __syncthreads();
    }
    if (tid == 0) g_is64 = (acc[0] == 0) ? 1 : 0;
}

// ---------------- CSR build ----------------
__global__ void zero_cnt_kernel() {
    int i = blockIdx.x * blockDim.x + threadIdx.x;
    if (i < N_NODES) g_cnt[i] = 0;
}

__global__ void decode_hist_kernel(const int* __restrict__ w) {
    int e = blockIdx.x * blockDim.x + threadIdx.x;
    if (e >= N_EDGES) return;
    int s, d;
    if (g_is64) {
        s = w[2 * e];
        d = w[2 * (N_EDGES + e)];
    } else {
        s = w[e];
        d = w[N_EDGES + e];
    }
    g_src[e] = s;
    g_dst[e] = d;
    atomicAdd(&g_cnt[d], 1);
}

__global__ void bsum_kernel() {
    __shared__ int sm[256];
    int i = blockIdx.x * 256 + threadIdx.x;
    sm[threadIdx.x] = (i < N_NODES) ? g_cnt[i] : 0;
    __syncthreads();
    for (int s = 128; s > 0; s >>= 1) {
        if (threadIdx.x < s) sm[threadIdx.x] += sm[threadIdx.x + s];
        __syncthreads();
    }
    if (threadIdx.x == 0) g_bsum[blockIdx.x] = sm[0];
}

__global__ void scan_bsum_kernel() {
    __shared__ int sm[512];
    int t = threadIdx.x;
    int val = (t < NB) ? g_bsum[t] : 0;
    sm[t] = val;
    __syncthreads();
    for (int off = 1; off < 512; off <<= 1) {
        int x = (t >= off) ? sm[t - off] : 0;
        __syncthreads();
        sm[t] += x;
        __syncthreads();
    }
    if (t < NB) g_bsum[t] = sm[t] - val;
}

__global__ void rowptr_kernel() {
    __shared__ int sm[256];
    int t = threadIdx.x;
    int i = blockIdx.x * 256 + t;
    int c = (i < N_NODES) ? g_cnt[i] : 0;
    sm[t] = c;
    __syncthreads();
    for (int off = 1; off < 256; off <<= 1) {
        int x = (t >= off) ? sm[t - off] : 0;
        __syncthreads();
        sm[t] += x;
        __syncthreads();
    }
    if (i < N_NODES) {
        int rp = g_bsum[blockIdx.x] + sm[t] - c;
        g_rowptr[i] = rp;
        g_cursor[i] = rp;
        if (i == N_NODES - 1) g_rowptr[N_NODES] = rp + c;
    }
}

__global__ void fill_kernel() {
    int e = blockIdx.x * blockDim.x + threadIdx.x;
    if (e >= N_EDGES) return;
    int pos = atomicAdd(&g_cursor[g_dst[e]], 1);
    g_esrc[pos] = g_src[e];
}

// ---------------- pack weights ----------------
__global__ void pack_all_kernel(const float* __restrict__ Wn0, const float* __restrict__ Wr0,
                                const float* __restrict__ Wn1, const float* __restrict__ Wr1,
                                const float* __restrict__ Wn2, const float* __restrict__ Wr2) {
    int idx = blockIdx.x * blockDim.x + threadIdx.x;
    if (idx >= 3 * 128 * 256) return;
    int layer = idx / (128 * 256);
    int r = idx % (128 * 256);
    int n = r / 256, k = r % 256;
    const float* Wn = (layer == 0) ? Wn0 : (layer == 1) ? Wn1 : Wn2;
    const float* Wr = (layer == 0) ? Wr0 : (layer == 1) ? Wr1 : Wr2;
    float w = (k < C) ? Wn[n * C + k] : Wr[n * C + (k - C)];
    __nv_bfloat16 hi = __float2bfloat16(w);
    __nv_bfloat16 lo = __float2bfloat16(w - __bfloat162float(hi));
    g_Bw[layer][0][r] = bfbits(hi);
    g_Bw[layer][1][r] = bfbits(lo);
}

__global__ void pack_head_kernel(const float* __restrict__ Wh1,
                                 const float* __restrict__ bh1) {
    int idx = blockIdx.x * blockDim.x + threadIdx.x;
    if (idx < 128 * 128) {
        int n = idx / 128, k = idx % 128;
        float w = (n < 64) ? Wh1[n * C + k] : 0.0f;
        __nv_bfloat16 hi = __float2bfloat16(w);
        __nv_bfloat16 lo = __float2bfloat16(w - __bfloat162float(hi));
        g_Bh[0][idx] = bfbits(hi);
        g_Bh[1][idx] = bfbits(lo);
    }
    if (idx < C) g_bh1p[idx] = (idx < 64) ? bh1[idx] : 0.0f;
}

// ---------------- CSR aggregation -> bf16 hi/lo planes ----------------
template <bool XFORM>
__global__ void agg_kernel(const float* __restrict__ h) {
    int gt = blockIdx.x * blockDim.x + threadIdx.x;
    int w = gt >> 5;
    int lane = gt & 31;
    if (w >= N_NODES) return;
    int beg = g_rowptr[w], end = g_rowptr[w + 1];
    float4 acc = make_float4(0.f, 0.f, 0.f, 0.f);
    float4 sc, sh;
    if (XFORM) {
        sc = reinterpret_cast<const float4*>(g_scale)[lane];
        sh = reinterpret_cast<const float4*>(g_shift)[lane];
    }
    int e = beg;
    for (; e + 1 < end; e += 2) {
        int s0 = __ldg(&g_esrc[e]);
        int s1 = __ldg(&g_esrc[e + 1]);
        float4 v0 = *reinterpret_cast<const float4*>(h + (size_t)s0 * C + lane * 4);
        float4 v1 = *reinterpret_cast<const float4*>(h + (size_t)s1 * C + lane * 4);
        if (XFORM) {
            v0.x = fmaxf(fmaf(v0.x, sc.x, sh.x), 0.f);
            v0.y = fmaxf(fmaf(v0.y, sc.y, sh.y), 0.f);
            v0.z = fmaxf(fmaf(v0.z, sc.z, sh.z), 0.f);
            v0.w = fmaxf(fmaf(v0.w, sc.w, sh.w), 0.f);
            v1.x = fmaxf(fmaf(v1.x, sc.x, sh.x), 0.f);
            v1.y = fmaxf(fmaf(v1.y, sc.y, sh.y), 0.f);
            v1.z = fmaxf(fmaf(v1.z, sc.z, sh.z), 0.f);
            v1.w = fmaxf(fmaf(v1.w, sc.w, sh.w), 0.f);
        }
        acc.x += v0.x + v1.x;
        acc.y += v0.y + v1.y;
        acc.z += v0.z + v1.z;
        acc.w += v0.w + v1.w;
    }
    if (e < end) {
        int s0 = __ldg(&g_esrc[e]);
        float4 v0 = *reinterpret_cast<const float4*>(h + (size_t)s0 * C + lane * 4);
        if (XFORM) {
            v0.x = fmaxf(fmaf(v0.x, sc.x, sh.x), 0.f);
            v0.y = fmaxf(fmaf(v0.y, sc.y, sh.y), 0.f);
            v0.z = fmaxf(fmaf(v0.z, sc.z, sh.z), 0.f);
            v0.w = fmaxf(fmaf(v0.w, sc.w, sh.w), 0.f);
        }
        acc.x += v0.x;
        acc.y += v0.y;
        acc.z += v0.z;
        acc.w += v0.w;
    }
    float rd = 1.f / fmaxf((float)(end - beg), 1.f);
    float v[4] = {acc.x * rd, acc.y * rd, acc.z * rd, acc.w * rd};
    uint32_t hw[2], lw[2];
#pragma unroll
    for (int j = 0; j < 2; j++) {
        __nv_bfloat16 h0 = __float2bfloat16(v[2 * j]);
        __nv_bfloat16 h1 = __float2bfloat16(v[2 * j + 1]);
        __nv_bfloat16 l0 = __float2bfloat16(v[2 * j] - __bfloat162float(h0));
        __nv_bfloat16 l1 = __float2bfloat16(v[2 * j + 1] - __bfloat162float(h1));
        hw[j] = (uint32_t)bfbits(h0) | ((uint32_t)bfbits(h1) << 16);
        lw[j] = (uint32_t)bfbits(l0) | ((uint32_t)bfbits(l1) << 16);
    }
    *reinterpret_cast<uint2*>(g_aggh + (size_t)w * C + lane * 4) = make_uint2(hw[0], hw[1]);
    *reinterpret_cast<uint2*>(g_aggl + (size_t)w * C + lane * 4) = make_uint2(lw[0], lw[1]);
}

// ---------------- mma.sync fused GEMM (R7 structure + bf16-A fast path + head fusion) ----------------
// smem: A_hi 18432 | A_lo 18432 | B_hi 18432 | B_lo 18432 | bias 512 | sc 512 | sh 512 | Wh2 512
#define AS_HI 0
#define AS_LO 18432
#define BS_HI 36864
#define BS_LO 55296
#define SMBIAS 73728
#define SMSC 74240
#define SMSH 74752
#define SMW2 75264
#define SM_TOTAL 75776
#define STAGE_LD 132

template <int KS, bool SAGE, bool XFORM, bool RELU_OUT, bool STATS, bool HEAD2>
__global__ void __launch_bounds__(256, 2)
gemm_mma_kernel(const float* __restrict__ A, const unsigned short* __restrict__ Bpk,
                const float* __restrict__ bias, float* __restrict__ out,
                const float* __restrict__ Wh2, const float* __restrict__ bh2) {
    constexpr int NCHUNK = KS / 64;
    extern __shared__ char sm[];
    uint32_t smb = smem_u32(sm);
    int tid = threadIdx.x;
    int wid = tid >> 5;
    int lane = tid & 31;
    int row0 = blockIdx.x * 128;

    if (tid < 32) {
        reinterpret_cast<float4*>(sm + SMBIAS)[tid] = reinterpret_cast<const float4*>(bias)[tid];
        if (XFORM) {
            reinterpret_cast<float4*>(sm + SMSC)[tid] = reinterpret_cast<const float4*>(g_scale)[tid];
            reinterpret_cast<float4*>(sm + SMSH)[tid] = reinterpret_cast<const float4*>(g_shift)[tid];
        }
        if (HEAD2)
            reinterpret_cast<float4*>(sm + SMW2)[tid] = reinterpret_cast<const float4*>(Wh2)[tid];
    }
    __syncthreads();   // params written by warp 0, read by all

    int arow = tid >> 1;
    int ahalf = tid & 1;
    int grow = row0 + arow;
    bool valid = grow < N_NODES;

    int m0 = (wid >> 1) * 32;
    int n0 = (wid & 1) * 64;

    uint32_t a_base[2], b_base[4];
#pragma unroll
    for (int mi = 0; mi < 2; mi++)
        a_base[mi] = smb + AS_HI + (uint32_t)(m0 + mi * 16 + (lane & 15)) * 144u +
                     ((lane >> 4) * 8u) * 2u;
#pragma unroll
    for (int g = 0; g < 4; g++) {
        uint32_t nidx = (uint32_t)(n0 + g * 16 + ((lane >> 4) << 3) + (lane & 7));
        uint32_t koff = (((lane >> 3) & 1) * 8u) * 2u;
        b_base[g] = smb + BS_HI + nidx * 144u + koff;
    }

    float acc[2][8][4];
#pragma unroll
    for (int mi = 0; mi < 2; mi++)
#pragma unroll
        for (int ni = 0; ni < 8; ni++)
#pragma unroll
            for (int r = 0; r < 4; r++) acc[mi][ni][r] = 0.f;

    for (int chunk = 0; chunk < NCHUNK; chunk++) {
        if (chunk > 0) __syncthreads();
        // B chunk copy (hi+lo)
        for (int i = tid; i < 1024; i += 256) {
            int r = i >> 3, cc = i & 7;
            *reinterpret_cast<uint4*>(sm + BS_HI + r * 144 + cc * 16) =
                *reinterpret_cast<const uint4*>(Bpk + (size_t)r * KS + chunk * 64 + cc * 8);
            *reinterpret_cast<uint4*>(sm + BS_LO + r * 144 + cc * 16) =
                *reinterpret_cast<const uint4*>(Bpk + (size_t)128 * KS + (size_t)r * KS +
                                                chunk * 64 + cc * 8);
        }
        // A chunk
        if (SAGE && chunk < 2) {
            // fast path: agg already bf16 hi/lo — pure copy
            uint32_t soff = arow * 144u + ahalf * 64u;
            if (valid) {
                size_t goff = (size_t)grow * C + chunk * 64 + ahalf * 32;
                const uint4* ph = reinterpret_cast<const uint4*>(g_aggh + goff);
                const uint4* pl = reinterpret_cast<const uint4*>(g_aggl + goff);
#pragma unroll
                for (int j = 0; j < 4; j++) {
                    *reinterpret_cast<uint4*>(sm + AS_HI + soff + j * 16) = ph[j];
                    *reinterpret_cast<uint4*>(sm + AS_LO + soff + j * 16) = pl[j];
                }
            } else {
#pragma unroll
                for (int j = 0; j < 4; j++) {
                    *reinterpret_cast<uint4*>(sm + AS_HI + soff + j * 16) = make_uint4(0, 0, 0, 0);
                    *reinterpret_cast<uint4*>(sm + AS_LO + soff + j * 16) = make_uint4(0, 0, 0, 0);
                }
            }
        } else {
            int col0 = (SAGE ? chunk * 64 - 128 : chunk * 64) + ahalf * 32;
            const float* ssc = reinterpret_cast<const float*>(sm + SMSC);
            const float* ssh = reinterpret_cast<const float*>(sm + SMSH);
#pragma unroll
            for (int j8 = 0; j8 < 4; j8++) {
                float v[8];
                if (valid) {
                    const float* srcp = A + (size_t)grow * C + col0 + j8 * 8;
                    *reinterpret_cast<float4*>(&v[0]) = *reinterpret_cast<const float4*>(srcp);
                    *reinterpret_cast<float4*>(&v[4]) = *reinterpret_cast<const float4*>(srcp + 4);
                    if (XFORM) {
                        int cb = col0 + j8 * 8;
#pragma unroll
                        for (int j = 0; j < 8; j++)
                            v[j] = fmaxf(fmaf(v[j], ssc[cb + j], ssh[cb + j]), 0.f);
                    }
                } else {
#pragma unroll
                    for (int j = 0; j < 8; j++) v[j] = 0.f;
                }
                uint32_t hw[4], lw[4];
#pragma unroll
                for (int j = 0; j < 4; j++) {
                    __nv_bfloat16 h0 = __float2bfloat16(v[2 * j]);
                    __nv_bfloat16 h1 = __float2bfloat16(v[2 * j + 1]);
                    __nv_bfloat16 l0 = __float2bfloat16(v[2 * j] - __bfloat162float(h0));
                    __nv_bfloat16 l1 = __float2bfloat16(v[2 * j + 1] - __bfloat162float(h1));
                    hw[j] = (uint32_t)bfbits(h0) | ((uint32_t)bfbits(h1) << 16);
                    lw[j] = (uint32_t)bfbits(l0) | ((uint32_t)bfbits(l1) << 16);
                }
                uint32_t off = arow * 144u + (ahalf * 32 + j8 * 8) * 2u;
                *reinterpret_cast<uint4*>(sm + AS_HI + off) = make_uint4(hw[0], hw[1], hw[2], hw[3]);
                *reinterpret_cast<uint4*>(sm + AS_LO + off) = make_uint4(lw[0], lw[1], lw[2], lw[3]);
            }
        }
        __syncthreads();

#pragma unroll
        for (int ks = 0; ks < 4; ks++) {
            int kl = ks * 16;
            uint32_t ah[2][4], al[2][4], bh[4][4], bl[4][4];
#pragma unroll
            for (int mi = 0; mi < 2; mi++) {
                ldm4(ah[mi], a_base[mi] + kl * 2);
                ldm4(al[mi], a_base[mi] + 18432 + kl * 2);
            }
#pragma unroll
            for (int g = 0; g < 4; g++) {
                ldm4(bh[g], b_base[g] + kl * 2);
                ldm4(bl[g], b_base[g] + 18432 + kl * 2);
            }
#pragma unroll
            for (int mi = 0; mi < 2; mi++)
#pragma unroll
                for (int g = 0; g < 4; g++) {
                    mma16816(acc[mi][2 * g + 0], ah[mi], bh[g][0], bh[g][1]);
                    mma16816(acc[mi][2 * g + 1], ah[mi], bh[g][2], bh[g][3]);
                    mma16816(acc[mi][2 * g + 0], ah[mi], bl[g][0], bl[g][1]);
                    mma16816(acc[mi][2 * g + 1], ah[mi], bl[g][2], bl[g][3]);
                    mma16816(acc[mi][2 * g + 0], al[mi], bh[g][0], bh[g][1]);
                    mma16816(acc[mi][2 * g + 1], al[mi], bh[g][2], bh[g][3]);
                }
        }
    }
    __syncthreads();   // all warps done before stage overlay

    // epilogue: bias (+relu), stage to smem (overlaying A/B regions)
    float* stage = reinterpret_cast<float*>(sm);
    const float* sbias = reinterpret_cast<const float*>(sm + SMBIAS);
    int qr = lane >> 2, qc = lane & 3;
#pragma unroll
    for (int mi = 0; mi < 2; mi++) {
        int mA = m0 + mi * 16 + qr;
        int mB = mA + 8;
        bool vA = (row0 + mA) < N_NODES;
        bool vB = (row0 + mB) < N_NODES;
#pragma unroll
        for (int ni = 0; ni < 8; ni++) {
            int n = n0 + ni * 8 + qc * 2;
            float2 pA, pB;
            pA.x = acc[mi][ni][0] + sbias[n];
            pA.y = acc[mi][ni][1] + sbias[n + 1];
            pB.x = acc[mi][ni][2] + sbias[n];
            pB.y = acc[mi][ni][3] + sbias[n + 1];
            if (RELU_OUT) {
                pA.x = fmaxf(pA.x, 0.f); pA.y = fmaxf(pA.y, 0.f);
                pB.x = fmaxf(pB.x, 0.f); pB.y = fmaxf(pB.y, 0.f);
            }
            if (!vA) pA = make_float2(0.f, 0.f);
            if (!vB) pB = make_float2(0.f, 0.f);
            *reinterpret_cast<float2*>(stage + mA * STAGE_LD + n) = pA;
            *reinterpret_cast<float2*>(stage + mB * STAGE_LD + n) = pB;
        }
    }
    __syncthreads();

    if (STATS && tid < C) {
        float s = 0.f, q = 0.f;
        for (int r = 0; r < 128; r++) {
            float v = stage[r * STAGE_LD + tid];
            s += v;
            q += v * v;
        }
        atomicAdd(&g_sum[tid], s);
        atomicAdd(&g_sumsq[tid], q);
    }

    if (HEAD2) {
        // fused head-2: out[row][c] = dot(stage[row][0:64], Wh2[c]) + bh2[c]
        const float* sw = reinterpret_cast<const float*>(sm + SMW2);
        if (tid < 128) {
            int row = row0 + tid;
            if (row < N_NODES) {
                float s0 = 0.f, s1 = 0.f;
                const float* rp = stage + tid * STAGE_LD;
#pragma unroll 16
                for (int k = 0; k < 64; k++) {
                    float v = rp[k];
                    s0 = fmaf(v, sw[k], s0);
                    s1 = fmaf(v, sw[64 + k], s1);
                }
                out[(size_t)row * 2 + 0] = s0 + __ldg(&bh2[0]);
                out[(size_t)row * 2 + 1] = s1 + __ldg(&bh2[1]);
            }
        }
    } else {
        for (int idx = tid; idx < 128 * 32; idx += 256) {
            int r = idx >> 5, c4 = idx & 31;
            int row = row0 + r;
            if (row >= N_NODES) continue;
            *reinterpret_cast<float4*>(out + (size_t)row * C + c4 * 4) =
                *reinterpret_cast<const float4*>(stage + r * STAGE_LD + c4 * 4);
        }
    }
}

__global__ void bnparam_kernel(const float* __restrict__ g, const float* __restrict__ be) {
    int c = threadIdx.x;
    if (c >= C) return;
    float m = g_sum[c] / (float)N_NODES;
    float v = g_sumsq[c] / (float)N_NODES - m * m;
    float sc = g[c] * rsqrtf(fmaxf(v, 0.f) + EPS_BN);
    g_scale[c] = sc;
    g_shift[c] = be[c] - m * sc;
    g_sum[c] = 0.f;
    g_sumsq[c] = 0.f;
}

// ---------------- launch ----------------
extern "C" void kernel_launch(void* const* d_in, const int* in_sizes, int n_in,
                              void* d_out, int out_size) {
    const float* x = (const float*)d_in[0];
    const int* ei32 = (const int*)d_in[1];
    const float* Wn[3] = {(const float*)d_in[2], (const float*)d_in[7], (const float*)d_in[12]};
    const float* bn[3] = {(const float*)d_in[3], (const float*)d_in[8], (const float*)d_in[13]};
    const float* Wr[3] = {(const float*)d_in[4], (const float*)d_in[9], (const float*)d_in[14]};
    const float* ga[3] = {(const float*)d_in[5], (const float*)d_in[10], (const float*)d_in[15]};
    const float* be[3] = {(const float*)d_in[6], (const float*)d_in[11], (const float*)d_in[16]};
    const float* Wh1 = (const float*)d_in[17];
    const float* bh1 = (const float*)d_in[18];
    const float* Wh2 = (const float*)d_in[19];
    const float* bh2 = (const float*)d_in[20];
    float* out = (float*)d_out;

    float *p_h1, *p_h2, *p_bh1p;
    unsigned short *p_Bw, *p_Bh;
    cudaGetSymbolAddress((void**)&p_h1, g_h1);
    cudaGetSymbolAddress((void**)&p_h2, g_h2);
    cudaGetSymbolAddress((void**)&p_Bw, g_Bw);
    cudaGetSymbolAddress((void**)&p_Bh, g_Bh);
    cudaGetSymbolAddress((void**)&p_bh1p, g_bh1p);

    cudaFuncSetAttribute(gemm_mma_kernel<256, true, false, false, true, false>,
                         cudaFuncAttributeMaxDynamicSharedMemorySize, SM_TOTAL);
    cudaFuncSetAttribute(gemm_mma_kernel<256, true, true, false, true, false>,
                         cudaFuncAttributeMaxDynamicSharedMemorySize, SM_TOTAL);
    cudaFuncSetAttribute(gemm_mma_kernel<128, false, true, true, false, true>,
                         cudaFuncAttributeMaxDynamicSharedMemorySize, SM_TOTAL);

    detect_kernel<<<1, 256>>>(ei32);
    zero_cnt_kernel<<<NB, 256>>>();
    decode_hist_kernel<<<(N_EDGES + 255) / 256, 256>>>(ei32);
    bsum_kernel<<<NB, 256>>>();
    scan_bsum_kernel<<<1, 512>>>();
    rowptr_kernel<<<NB, 256>>>();
    fill_kernel<<<(N_EDGES + 255) / 256, 256>>>();
    pack_all_kernel<<<(3 * 128 * 256 + 255) / 256, 256>>>(
        Wn[0], Wr[0], Wn[1], Wr[1], Wn[2], Wr[2]);
    pack_head_kernel<<<(128 * 128 + 255) / 256, 256>>>(Wh1, bh1);

    const int gemm_blocks = (N_NODES + 127) / 128;
    const int agg_blocks = (N_NODES * 32 + 255) / 256;
    float* bufs[2] = {p_h1, p_h2};
    const float* h_in = x;

    for (int l = 0; l < 3; l++) {
        float* h_out = bufs[l & 1];
        if (l == 0) {
            agg_kernel<false><<<agg_blocks, 256>>>(h_in);
            gemm_mma_kernel<256, true, false, false, true, false><<<gemm_blocks, 256, SM_TOTAL>>>(
                h_in, p_Bw, bn[l], h_out, nullptr, nullptr);
        } else {
            agg_kernel<true><<<agg_blocks, 256>>>(h_in);
            gemm_mma_kernel<256, true, true, false, true, false><<<gemm_blocks, 256, SM_TOTAL>>>(
                h_in, p_Bw + (size_t)l * 2 * 128 * 256, bn[l], h_out, nullptr, nullptr);
        }
        bnparam_kernel<<<1, 128>>>(ga[l], be[l]);
        h_in = h_out;
    }

    // head: layer-2 raw output in bufs[0]=g_h1; BN+ReLU on A-load; head-2 fused in epilogue.
    gemm_mma_kernel<128, false, true, true, false, true><<<gemm_blocks, 256, SM_TOTAL>>>(
        p_h1, p_Bh, p_bh1p, out, Wh2, bh2);
}

// round 12
// speedup vs baseline: 1.2315x; 1.0479x over previous
#include <cuda_runtime.h>
#include <cuda_bf16.h>
#include <cstdint>

#define N_NODES 100000
#define N_EDGES 800000
#define C 128
#define EPS_BN 1e-5f
#define NB ((N_NODES + 255) / 256)

// ---------------- device scratch (no allocs allowed) ----------------
__device__ unsigned short g_aggh[N_NODES * C];   // mean, bf16 hi plane
__device__ unsigned short g_aggl[N_NODES * C];   // mean, bf16 lo plane
__device__ float g_h1[N_NODES * C];
__device__ float g_h2[N_NODES * C];
__device__ unsigned short g_Bw[3][2][128 * 256]; // [layer][hi/lo][n][k] bf16
__device__ unsigned short g_Bh[2][128 * 128];    // head [hi/lo][n][k]
__device__ float g_bh1p[C];
__device__ float g_sum[C];
__device__ float g_sumsq[C];
__device__ float g_scale[C];
__device__ float g_shift[C];
__device__ int g_src[N_EDGES];
__device__ int g_dst[N_EDGES];
__device__ int g_esrc[N_EDGES];
__device__ int g_cnt[N_NODES];
__device__ int g_rowptr[N_NODES + 1];
__device__ int g_cursor[N_NODES];
__device__ int g_bsum[NB];
__device__ int g_is64;

// ---------------- helpers ----------------
__device__ __forceinline__ uint32_t smem_u32(const void* p) {
    uint32_t a;
    asm("{ .reg .u64 t; cvta.to.shared.u64 t, %1; cvt.u32.u64 %0, t; }" : "=r"(a) : "l"(p));
    return a;
}
__device__ __forceinline__ void ldm4(uint32_t* r, uint32_t addr) {
    asm volatile("ldmatrix.sync.aligned.m8n8.x4.shared.b16 {%0,%1,%2,%3}, [%4];"
                 : "=r"(r[0]), "=r"(r[1]), "=r"(r[2]), "=r"(r[3]) : "r"(addr));
}
__device__ __forceinline__ void mma16816(float* c, const uint32_t* a, uint32_t b0, uint32_t b1) {
    asm volatile(
        "mma.sync.aligned.m16n8k16.row.col.f32.bf16.bf16.f32 "
        "{%0,%1,%2,%3}, {%4,%5,%6,%7}, {%8,%9}, {%0,%1,%2,%3};"
        : "+f"(c[0]), "+f"(c[1]), "+f"(c[2]), "+f"(c[3])
        : "r"(a[0]), "r"(a[1]), "r"(a[2]), "r"(a[3]), "r"(b0), "r"(b1));
}
__device__ __forceinline__ unsigned short bfbits(__nv_bfloat16 h) {
    return *reinterpret_cast<unsigned short*>(&h);
}
// pack two floats into bf16x2 (rn)
__device__ __forceinline__ uint32_t bf16x2(float lo, float hi) {
    uint32_t r;
    asm("cvt.rn.bf16x2.f32 %0, %1, %2;" : "=r"(r) : "f"(hi), "f"(lo));
    return r;
}
// reconstruct the two fp32 values a bf16x2 word represents
__device__ __forceinline__ void bf16x2_to_f32(uint32_t w, float& lo, float& hi) {
    uint32_t l = w << 16, h = w & 0xffff0000u;
    lo = __uint_as_float(l);
    hi = __uint_as_float(h);
}

// ---------------- detect edge dtype + zero cnt (merged) ----------------
__global__ void detect_zero_kernel(const int* __restrict__ w) {
    if (blockIdx.x < NB) {
        int i = blockIdx.x * 256 + threadIdx.x;
        if (i < N_NODES) g_cnt[i] = 0;
        return;
    }
    __shared__ int acc[256];
    int tid = threadIdx.x;
    int v = 0;
    for (int i = tid; i < 1024; i += 256) v |= w[2 * i + 1];
    acc[tid] = v;
    __syncthreads();
    for (int s = 128; s > 0; s >>= 1) {
        if (tid < s) acc[tid] |= acc[tid + s];
        __syncthreads();
    }
    if (tid == 0) g_is64 = (acc[0] == 0) ? 1 : 0;
}

// ---------------- CSR build ----------------
__global__ void decode_hist_kernel(const int* __restrict__ w) {
    int e = blockIdx.x * blockDim.x + threadIdx.x;
    if (e >= N_EDGES) return;
    int s, d;
    if (g_is64) {
        s = w[2 * e];
        d = w[2 * (N_EDGES + e)];
    } else {
        s = w[e];
        d = w[N_EDGES + e];
    }
    g_src[e] = s;
    g_dst[e] = d;
    atomicAdd(&g_cnt[d], 1);
}

__global__ void bsum_kernel() {
    __shared__ int sm[256];
    int i = blockIdx.x * 256 + threadIdx.x;
    sm[threadIdx.x] = (i < N_NODES) ? g_cnt[i] : 0;
    __syncthreads();
    for (int s = 128; s > 0; s >>= 1) {
        if (threadIdx.x < s) sm[threadIdx.x] += sm[threadIdx.x + s];
        __syncthreads();
    }
    if (threadIdx.x == 0) g_bsum[blockIdx.x] = sm[0];
}

__global__ void scan_bsum_kernel() {
    __shared__ int sm[512];
    int t = threadIdx.x;
    int val = (t < NB) ? g_bsum[t] : 0;
    sm[t] = val;
    __syncthreads();
    for (int off = 1; off < 512; off <<= 1) {
        int x = (t >= off) ? sm[t - off] : 0;
        __syncthreads();
        sm[t] += x;
        __syncthreads();
    }
    if (t < NB) g_bsum[t] = sm[t] - val;
}

__global__ void rowptr_kernel() {
    __shared__ int sm[256];
    int t = threadIdx.x;
    int i = blockIdx.x * 256 + t;
    int c = (i < N_NODES) ? g_cnt[i] : 0;
    sm[t] = c;
    __syncthreads();
    for (int off = 1; off < 256; off <<= 1) {
        int x = (t >= off) ? sm[t - off] : 0;
        __syncthreads();
        sm[t] += x;
        __syncthreads();
    }
    if (i < N_NODES) {
        int rp = g_bsum[blockIdx.x] + sm[t] - c;
        g_rowptr[i] = rp;
        g_cursor[i] = rp;
        if (i == N_NODES - 1) g_rowptr[N_NODES] = rp + c;
    }
}

__global__ void fill_kernel() {
    int e = blockIdx.x * blockDim.x + threadIdx.x;
    if (e >= N_EDGES) return;
    int pos = atomicAdd(&g_cursor[g_dst[e]], 1);
    g_esrc[pos] = g_src[e];
}

// ---------------- pack all weights (layers + head, merged) ----------------
__global__ void pack_all_kernel(const float* __restrict__ Wn0, const float* __restrict__ Wr0,
                                const float* __restrict__ Wn1, const float* __restrict__ Wr1,
                                const float* __restrict__ Wn2, const float* __restrict__ Wr2,
                                const float* __restrict__ Wh1, const float* __restrict__ bh1) {
    int idx = blockIdx.x * blockDim.x + threadIdx.x;
    if (idx < 3 * 128 * 256) {
        int layer = idx / (128 * 256);
        int r = idx % (128 * 256);
        int n = r / 256, k = r % 256;
        const float* Wn = (layer == 0) ? Wn0 : (layer == 1) ? Wn1 : Wn2;
        const float* Wr = (layer == 0) ? Wr0 : (layer == 1) ? Wr1 : Wr2;
        float w = (k < C) ? Wn[n * C + k] : Wr[n * C + (k - C)];
        __nv_bfloat16 hi = __float2bfloat16(w);
        __nv_bfloat16 lo = __float2bfloat16(w - __bfloat162float(hi));
        g_Bw[layer][0][r] = bfbits(hi);
        g_Bw[layer][1][r] = bfbits(lo);
    } else {
        int r = idx - 3 * 128 * 256;
        if (r < 128 * 128) {
            int n = r / 128, k = r % 128;
            float w = (n < 64) ? Wh1[n * C + k] : 0.0f;
            __nv_bfloat16 hi = __float2bfloat16(w);
            __nv_bfloat16 lo = __float2bfloat16(w - __bfloat162float(hi));
            g_Bh[0][r] = bfbits(hi);
            g_Bh[1][r] = bfbits(lo);
        } else if (r - 128 * 128 < C) {
            int c = r - 128 * 128;
            g_bh1p[c] = (c < 64) ? bh1[c] : 0.0f;
        }
    }
}

// ---------------- CSR aggregation -> bf16 hi/lo planes (4-way unrolled gather) ----------------
template <bool XFORM>
__global__ void agg_kernel(const float* __restrict__ h) {
    int gt = blockIdx.x * blockDim.x + threadIdx.x;
    int w = gt >> 5;
    int lane = gt & 31;
    if (w >= N_NODES) return;
    int beg = g_rowptr[w], end = g_rowptr[w + 1];
    float4 acc = make_float4(0.f, 0.f, 0.f, 0.f);
    float4 sc, sh;
    if (XFORM) {
        sc = reinterpret_cast<const float4*>(g_scale)[lane];
        sh = reinterpret_cast<const float4*>(g_shift)[lane];
    }
    auto xf = [&](float4& v) {
        if (XFORM) {
            v.x = fmaxf(fmaf(v.x, sc.x, sh.x), 0.f);
            v.y = fmaxf(fmaf(v.y, sc.y, sh.y), 0.f);
            v.z = fmaxf(fmaf(v.z, sc.z, sh.z), 0.f);
            v.w = fmaxf(fmaf(v.w, sc.w, sh.w), 0.f);
        }
    };
    int e = beg;
    for (; e + 3 < end; e += 4) {
        int s0 = __ldg(&g_esrc[e]);
        int s1 = __ldg(&g_esrc[e + 1]);
        int s2 = __ldg(&g_esrc[e + 2]);
        int s3 = __ldg(&g_esrc[e + 3]);
        float4 v0 = *reinterpret_cast<const float4*>(h + (size_t)s0 * C + lane * 4);
        float4 v1 = *reinterpret_cast<const float4*>(h + (size_t)s1 * C + lane * 4);
        float4 v2 = *reinterpret_cast<const float4*>(h + (size_t)s2 * C + lane * 4);
        float4 v3 = *reinterpret_cast<const float4*>(h + (size_t)s3 * C + lane * 4);
        xf(v0); xf(v1); xf(v2); xf(v3);
        acc.x += (v0.x + v1.x) + (v2.x + v3.x);
        acc.y += (v0.y + v1.y) + (v2.y + v3.y);
        acc.z += (v0.z + v1.z) + (v2.z + v3.z);
        acc.w += (v0.w + v1.w) + (v2.w + v3.w);
    }
    for (; e < end; e++) {
        int s0 = __ldg(&g_esrc[e]);
        float4 v0 = *reinterpret_cast<const float4*>(h + (size_t)s0 * C + lane * 4);
        xf(v0);
        acc.x += v0.x;
        acc.y += v0.y;
        acc.z += v0.z;
        acc.w += v0.w;
    }
    float rd = 1.f / fmaxf((float)(end - beg), 1.f);
    float v[4] = {acc.x * rd, acc.y * rd, acc.z * rd, acc.w * rd};
    uint32_t hw[2], lw[2];
#pragma unroll
    for (int j = 0; j < 2; j++) {
        uint32_t hp = bf16x2(v[2 * j], v[2 * j + 1]);
        float r0, r1;
        bf16x2_to_f32(hp, r0, r1);
        uint32_t lp = bf16x2(v[2 * j] - r0, v[2 * j + 1] - r1);
        hw[j] = hp;
        lw[j] = lp;
    }
    *reinterpret_cast<uint2*>(g_aggh + (size_t)w * C + lane * 4) = make_uint2(hw[0], hw[1]);
    *reinterpret_cast<uint2*>(g_aggl + (size_t)w * C + lane * 4) = make_uint2(lw[0], lw[1]);
}

// ---------------- mma.sync fused GEMM ----------------
// smem: A_hi 18432 | A_lo 18432 | B_hi 18432 | B_lo 18432 | bias 512 | sc 512 | sh 512 | Wh2 512
#define AS_HI 0
#define AS_LO 18432
#define BS_HI 36864
#define BS_LO 55296
#define SMBIAS 73728
#define SMSC 74240
#define SMSH 74752
#define SMW2 75264
#define SM_TOTAL 75776
#define STAGE_LD 132

template <int KS, bool SAGE, bool XFORM, bool RELU_OUT, bool STATS, bool HEAD2>
__global__ void __launch_bounds__(256, 2)
gemm_mma_kernel(const float* __restrict__ A, const unsigned short* __restrict__ Bpk,
                const float* __restrict__ bias, float* __restrict__ out,
                const float* __restrict__ Wh2, const float* __restrict__ bh2) {
    constexpr int NCHUNK = KS / 64;
    extern __shared__ char sm[];
    uint32_t smb = smem_u32(sm);
    int tid = threadIdx.x;
    int wid = tid >> 5;
    int lane = tid & 31;
    int row0 = blockIdx.x * 128;

    if (tid < 32) {
        reinterpret_cast<float4*>(sm + SMBIAS)[tid] = reinterpret_cast<const float4*>(bias)[tid];
        if (XFORM) {
            reinterpret_cast<float4*>(sm + SMSC)[tid] = reinterpret_cast<const float4*>(g_scale)[tid];
            reinterpret_cast<float4*>(sm + SMSH)[tid] = reinterpret_cast<const float4*>(g_shift)[tid];
        }
        if (HEAD2)
            reinterpret_cast<float4*>(sm + SMW2)[tid] = reinterpret_cast<const float4*>(Wh2)[tid];
    }
    __syncthreads();   // params written by warp 0, read by all

    int arow = tid >> 1;
    int ahalf = tid & 1;
    int grow = row0 + arow;
    bool valid = grow < N_NODES;

    int m0 = (wid >> 1) * 32;
    int n0 = (wid & 1) * 64;

    uint32_t a_base[2], b_base[4];
#pragma unroll
    for (int mi = 0; mi < 2; mi++)
        a_base[mi] = smb + AS_HI + (uint32_t)(m0 + mi * 16 + (lane & 15)) * 144u +
                     ((lane >> 4) * 8u) * 2u;
#pragma unroll
    for (int g = 0; g < 4; g++) {
        uint32_t nidx = (uint32_t)(n0 + g * 16 + ((lane >> 4) << 3) + (lane & 7));
        uint32_t koff = (((lane >> 3) & 1) * 8u) * 2u;
        b_base[g] = smb + BS_HI + nidx * 144u + koff;
    }

    float acc[2][8][4];
#pragma unroll
    for (int mi = 0; mi < 2; mi++)
#pragma unroll
        for (int ni = 0; ni < 8; ni++)
#pragma unroll
            for (int r = 0; r < 4; r++) acc[mi][ni][r] = 0.f;

    for (int chunk = 0; chunk < NCHUNK; chunk++) {
        if (chunk > 0) __syncthreads();
        // B chunk copy (hi+lo)
        for (int i = tid; i < 1024; i += 256) {
            int r = i >> 3, cc = i & 7;
            *reinterpret_cast<uint4*>(sm + BS_HI + r * 144 + cc * 16) =
                *reinterpret_cast<const uint4*>(Bpk + (size_t)r * KS + chunk * 64 + cc * 8);
            *reinterpret_cast<uint4*>(sm + BS_LO + r * 144 + cc * 16) =
                *reinterpret_cast<const uint4*>(Bpk + (size_t)128 * KS + (size_t)r * KS +
                                                chunk * 64 + cc * 8);
        }
        // A chunk
        if (SAGE && chunk < 2) {
            // fast path: agg already bf16 hi/lo — pure copy
            uint32_t soff = arow * 144u + ahalf * 64u;
            if (valid) {
                size_t goff = (size_t)grow * C + chunk * 64 + ahalf * 32;
                const uint4* ph = reinterpret_cast<const uint4*>(g_aggh + goff);
                const uint4* pl = reinterpret_cast<const uint4*>(g_aggl + goff);
#pragma unroll
                for (int j = 0; j < 4; j++) {
                    *reinterpret_cast<uint4*>(sm + AS_HI + soff + j * 16) = ph[j];
                    *reinterpret_cast<uint4*>(sm + AS_LO + soff + j * 16) = pl[j];
                }
            } else {
#pragma unroll
                for (int j = 0; j < 4; j++) {
                    *reinterpret_cast<uint4*>(sm + AS_HI + soff + j * 16) = make_uint4(0, 0, 0, 0);
                    *reinterpret_cast<uint4*>(sm + AS_LO + soff + j * 16) = make_uint4(0, 0, 0, 0);
                }
            }
        } else {
            int col0 = (SAGE ? chunk * 64 - 128 : chunk * 64) + ahalf * 32;
            const float* ssc = reinterpret_cast<const float*>(sm + SMSC);
            const float* ssh = reinterpret_cast<const float*>(sm + SMSH);
#pragma unroll
            for (int j8 = 0; j8 < 4; j8++) {
                float v[8];
                if (valid) {
                    const float* srcp = A + (size_t)grow * C + col0 + j8 * 8;
                    *reinterpret_cast<float4*>(&v[0]) = *reinterpret_cast<const float4*>(srcp);
                    *reinterpret_cast<float4*>(&v[4]) = *reinterpret_cast<const float4*>(srcp + 4);
                    if (XFORM) {
                        int cb = col0 + j8 * 8;
#pragma unroll
                        for (int j = 0; j < 8; j++)
                            v[j] = fmaxf(fmaf(v[j], ssc[cb + j], ssh[cb + j]), 0.f);
                    }
                } else {
#pragma unroll
                    for (int j = 0; j < 8; j++) v[j] = 0.f;
                }
                uint32_t hw[4], lw[4];
#pragma unroll
                for (int j = 0; j < 4; j++) {
                    uint32_t hp = bf16x2(v[2 * j], v[2 * j + 1]);
                    float r0, r1;
                    bf16x2_to_f32(hp, r0, r1);
                    uint32_t lp = bf16x2(v[2 * j] - r0, v[2 * j + 1] - r1);
                    hw[j] = hp;
                    lw[j] = lp;
                }
                uint32_t off = arow * 144u + (ahalf * 32 + j8 * 8) * 2u;
                *reinterpret_cast<uint4*>(sm + AS_HI + off) = make_uint4(hw[0], hw[1], hw[2], hw[3]);
                *reinterpret_cast<uint4*>(sm + AS_LO + off) = make_uint4(lw[0], lw[1], lw[2], lw[3]);
            }
        }
        __syncthreads();

#pragma unroll
        for (int ks = 0; ks < 4; ks++) {
            int kl = ks * 16;
            uint32_t ah[2][4], al[2][4], bh[4][4], bl[4][4];
#pragma unroll
            for (int mi = 0; mi < 2; mi++) {
                ldm4(ah[mi], a_base[mi] + kl * 2);
                ldm4(al[mi], a_base[mi] + 18432 + kl * 2);
            }
#pragma unroll
            for (int g = 0; g < 4; g++) {
                ldm4(bh[g], b_base[g] + kl * 2);
                ldm4(bl[g], b_base[g] + 18432 + kl * 2);
            }
#pragma unroll
            for (int mi = 0; mi < 2; mi++)
#pragma unroll
                for (int g = 0; g < 4; g++) {
                    mma16816(acc[mi][2 * g + 0], ah[mi], bh[g][0], bh[g][1]);
                    mma16816(acc[mi][2 * g + 1], ah[mi], bh[g][2], bh[g][3]);
                    mma16816(acc[mi][2 * g + 0], ah[mi], bl[g][0], bl[g][1]);
                    mma16816(acc[mi][2 * g + 1], ah[mi], bl[g][2], bl[g][3]);
                    mma16816(acc[mi][2 * g + 0], al[mi], bh[g][0], bh[g][1]);
                    mma16816(acc[mi][2 * g + 1], al[mi], bh[g][2], bh[g][3]);
                }
        }
    }
    __syncthreads();   // all warps done before stage overlay

    // epilogue: bias (+relu), stage to smem (overlaying A/B regions)
    float* stage = reinterpret_cast<float*>(sm);
    const float* sbias = reinterpret_cast<const float*>(sm + SMBIAS);
    int qr = lane >> 2, qc = lane & 3;
#pragma unroll
    for (int mi = 0; mi < 2; mi++) {
        int mA = m0 + mi * 16 + qr;
        int mB = mA + 8;
        bool vA = (row0 + mA) < N_NODES;
        bool vB = (row0 + mB) < N_NODES;
#pragma unroll
        for (int ni = 0; ni < 8; ni++) {
            int n = n0 + ni * 8 + qc * 2;
            float2 pA, pB;
            pA.x = acc[mi][ni][0] + sbias[n];
            pA.y = acc[mi][ni][1] + sbias[n + 1];
            pB.x = acc[mi][ni][2] + sbias[n];
            pB.y = acc[mi][ni][3] + sbias[n + 1];
            if (RELU_OUT) {
                pA.x = fmaxf(pA.x, 0.f); pA.y = fmaxf(pA.y, 0.f);
                pB.x = fmaxf(pB.x, 0.f); pB.y = fmaxf(pB.y, 0.f);
            }
            if (!vA) pA = make_float2(0.f, 0.f);
            if (!vB) pB = make_float2(0.f, 0.f);
            *reinterpret_cast<float2*>(stage + mA * STAGE_LD + n) = pA;
            *reinterpret_cast<float2*>(stage + mB * STAGE_LD + n) = pB;
        }
    }
    __syncthreads();

    if (STATS && tid < C) {
        float s = 0.f, q = 0.f;
        for (int r = 0; r < 128; r++) {
            float v = stage[r * STAGE_LD + tid];
            s += v;
            q += v * v;
        }
        atomicAdd(&g_sum[tid], s);
        atomicAdd(&g_sumsq[tid], q);
    }

    if (HEAD2) {
        // fused head-2: out[row][c] = dot(stage[row][0:64], Wh2[c]) + bh2[c]
        const float* sw = reinterpret_cast<const float*>(sm + SMW2);
        if (tid < 128) {
            int row = row0 + tid;
            if (row < N_NODES) {
                float s0 = 0.f, s1 = 0.f;
                const float* rp = stage + tid * STAGE_LD;
#pragma unroll 16
                for (int k = 0; k < 64; k++) {
                    float v = rp[k];
                    s0 = fmaf(v, sw[k], s0);
                    s1 = fmaf(v, sw[64 + k], s1);
                }
                out[(size_t)row * 2 + 0] = s0 + __ldg(&bh2[0]);
                out[(size_t)row * 2 + 1] = s1 + __ldg(&bh2[1]);
            }
        }
    } else {
        for (int idx = tid; idx < 128 * 32; idx += 256) {
            int r = idx >> 5, c4 = idx & 31;
            int row = row0 + r;
            if (row >= N_NODES) continue;
            *reinterpret_cast<float4*>(out + (size_t)row * C + c4 * 4) =
                *reinterpret_cast<const float4*>(stage + r * STAGE_LD + c4 * 4);
        }
    }
}

__global__ void bnparam_kernel(const float* __restrict__ g, const float* __restrict__ be) {
    int c = threadIdx.x;
    if (c >= C) return;
    float m = g_sum[c] / (float)N_NODES;
    float v = g_sumsq[c] / (float)N_NODES - m * m;
    float sc = g[c] * rsqrtf(fmaxf(v, 0.f) + EPS_BN);
    g_scale[c] = sc;
    g_shift[c] = be[c] - m * sc;
    g_sum[c] = 0.f;
    g_sumsq[c] = 0.f;
}

// ---------------- launch ----------------
extern "C" void kernel_launch(void* const* d_in, const int* in_sizes, int n_in,
                              void* d_out, int out_size) {
    const float* x = (const float*)d_in[0];
    const int* ei32 = (const int*)d_in[1];
    const float* Wn[3] = {(const float*)d_in[2], (const float*)d_in[7], (const float*)d_in[12]};
    const float* bn[3] = {(const float*)d_in[3], (const float*)d_in[8], (const float*)d_in[13]};
    const float* Wr[3] = {(const float*)d_in[4], (const float*)d_in[9], (const float*)d_in[14]};
    const float* ga[3] = {(const float*)d_in[5], (const float*)d_in[10], (const float*)d_in[15]};
    const float* be[3] = {(const float*)d_in[6], (const float*)d_in[11], (const float*)d_in[16]};
    const float* Wh1 = (const float*)d_in[17];
    const float* bh1 = (const float*)d_in[18];
    const float* Wh2 = (const float*)d_in[19];
    const float* bh2 = (const float*)d_in[20];
    float* out = (float*)d_out;

    float *p_h1, *p_h2, *p_bh1p;
    unsigned short *p_Bw, *p_Bh;
    cudaGetSymbolAddress((void**)&p_h1, g_h1);
    cudaGetSymbolAddress((void**)&p_h2, g_h2);
    cudaGetSymbolAddress((void**)&p_Bw, g_Bw);
    cudaGetSymbolAddress((void**)&p_Bh, g_Bh);
    cudaGetSymbolAddress((void**)&p_bh1p, g_bh1p);

    cudaFuncSetAttribute(gemm_mma_kernel<256, true, false, false, true, false>,
                         cudaFuncAttributeMaxDynamicSharedMemorySize, SM_TOTAL);
    cudaFuncSetAttribute(gemm_mma_kernel<256, true, true, false, true, false>,
                         cudaFuncAttributeMaxDynamicSharedMemorySize, SM_TOTAL);
    cudaFuncSetAttribute(gemm_mma_kernel<128, false, true, true, false, true>,
                         cudaFuncAttributeMaxDynamicSharedMemorySize, SM_TOTAL);

    detect_zero_kernel<<<NB + 1, 256>>>(ei32);
    decode_hist_kernel<<<(N_EDGES + 255) / 256, 256>>>(ei32);
    bsum_kernel<<<NB, 256>>>();
    scan_bsum_kernel<<<1, 512>>>();
    rowptr_kernel<<<NB, 256>>>();
    fill_kernel<<<(N_EDGES + 255) / 256, 256>>>();
    pack_all_kernel<<<(3 * 128 * 256 + 128 * 128 + C + 255) / 256, 256>>>(
        Wn[0], Wr[0], Wn[1], Wr[1], Wn[2], Wr[2], Wh1, bh1);

    const int gemm_blocks = (N_NODES + 127) / 128;
    const int agg_blocks = (N_NODES * 32 + 255) / 256;
    float* bufs[2] = {p_h1, p_h2};
    const float* h_in = x;

    for (int l = 0; l < 3; l++) {
        float* h_out = bufs[l & 1];
        if (l == 0) {
            agg_kernel<false><<<agg_blocks, 256>>>(h_in);
            gemm_mma_kernel<256, true, false, false, true, false><<<gemm_blocks, 256, SM_TOTAL>>>(
                h_in, p_Bw, bn[l], h_out, nullptr, nullptr);
        } else {
            agg_kernel<true><<<agg_blocks, 256>>>(h_in);
            gemm_mma_kernel<256, true, true, false, true, false><<<gemm_blocks, 256, SM_TOTAL>>>(
                h_in, p_Bw + (size_t)l * 2 * 128 * 256, bn[l], h_out, nullptr, nullptr);
        }
        bnparam_kernel<<<1, 128>>>(ga[l], be[l]);
        h_in = h_out;
    }

    // head: layer-2 raw output in bufs[0]=g_h1; BN+ReLU on A-load; head-2 fused in epilogue.
    gemm_mma_kernel<128, false, true, true, false, true><<<gemm_blocks, 256, SM_TOTAL>>>(
        p_h1, p_Bh, p_bh1p, out, Wh2, bh2);
}